// round 14
// baseline (speedup 1.0000x reference)
#include <cuda_runtime.h>
#include <cuda_bf16.h>
#include <cstdint>

#define CDIM 128
#define NS1 74
#define PQ 72   // bf16 tile pitch (144B): k1

__device__ float g_part[2][80][64][CDIM];   // 5.2 MB
__device__ float g_UV[2][64][CDIM];
__device__ float g_PR[2][64][CDIM];

// ---------------------------------------------------------------------------
// helpers (bf16 path for k1)
// ---------------------------------------------------------------------------
__device__ __forceinline__ unsigned sadr(const void* p) {
    return (unsigned)__cvta_generic_to_shared(p);
}
__device__ __forceinline__ uint32_t pk2(float x0, float x1) {
    uint32_t d;
    asm("cvt.rn.bf16x2.f32 %0, %2, %1;" : "=r"(d) : "f"(x0), "f"(x1));
    return d;
}
__device__ __forceinline__ float bfr(float x) {
    return __bfloat162float(__float2bfloat16(x));
}
__device__ __forceinline__ void cvst(unsigned short* hp, unsigned short* lp, float4 a) {
    ((uint32_t*)hp)[0] = pk2(a.x, a.y);
    ((uint32_t*)hp)[1] = pk2(a.z, a.w);
    float l0 = a.x - bfr(a.x), l1 = a.y - bfr(a.y);
    float l2 = a.z - bfr(a.z), l3 = a.w - bfr(a.w);
    ((uint32_t*)lp)[0] = pk2(l0, l1);
    ((uint32_t*)lp)[1] = pk2(l2, l3);
}
__device__ __forceinline__ void ldmAT(uint32_t* a, unsigned addr) {
    asm volatile("ldmatrix.sync.aligned.m8n8.x4.trans.shared.b16 {%0,%1,%2,%3},[%4];"
        : "=r"(a[0]), "=r"(a[1]), "=r"(a[2]), "=r"(a[3]) : "r"(addr));
}
__device__ __forceinline__ void ldmBT(uint32_t* b, unsigned addr) {
    asm volatile("ldmatrix.sync.aligned.m8n8.x2.trans.shared.b16 {%0,%1},[%2];"
        : "=r"(b[0]), "=r"(b[1]) : "r"(addr));
}
__device__ __forceinline__ void mma(float* d, const uint32_t* a, const uint32_t* b) {
    asm volatile("mma.sync.aligned.m16n8k16.row.col.f32.bf16.bf16.f32 "
        "{%0,%1,%2,%3},{%4,%5,%6,%7},{%8,%9},{%0,%1,%2,%3};"
        : "+f"(d[0]), "+f"(d[1]), "+f"(d[2]), "+f"(d[3])
        : "r"(a[0]), "r"(a[1]), "r"(a[2]), "r"(a[3]), "r"(b[0]), "r"(b[1]));
}
#define NEG4(dst, src) { dst[0]=src[0]^0x80008000u; dst[1]=src[1]^0x80008000u; \
                         dst[2]=src[2]^0x80008000u; dst[3]=src[3]^0x80008000u; }

// tf32 helpers (k3)
__device__ __forceinline__ uint32_t tf32c(float x) {
    uint32_t r; asm("cvt.rna.tf32.f32 %0, %1;" : "=r"(r) : "f"(x)); return r;
}
__device__ __forceinline__ void mma_tf32(float* d, const uint32_t* a, const uint32_t* b) {
    asm volatile("mma.sync.aligned.m16n8k8.row.col.f32.tf32.tf32.f32 "
        "{%0,%1,%2,%3},{%4,%5,%6,%7},{%8,%9},{%0,%1,%2,%3};"
        : "+f"(d[0]), "+f"(d[1]), "+f"(d[2]), "+f"(d[3])
        : "r"(a[0]), "r"(a[1]), "r"(a[2]), "r"(a[3]), "r"(b[0]), "r"(b[1]));
}

// ---------------------------------------------------------------------------
// Kernel 1 (R11 proven config): U/V partials via bf16 3-pass mma.sync.
// grid (74, 2 c-halves), block 256: 8 warps = 4 k-slabs(16) x 2 c-sub(32).
// ---------------------------------------------------------------------------
__global__ __launch_bounds__(256, 1) void k1_partial(
    const float* __restrict__ Qr, const float* __restrict__ Qi,
    const float* __restrict__ re, const float* __restrict__ im, int N)
{
    __shared__ unsigned short sQrh[32][PQ], sQrl[32][PQ], sQih[32][PQ], sQil[32][PQ];
    __shared__ unsigned short sXrh[32][PQ], sXrl[32][PQ], sXih[32][PQ], sXil[32][PQ];

    const int s  = blockIdx.x;
    const int c0 = blockIdx.y * 64;
    const int tid = threadIdx.x;
    const int nchunks = (N + 31) >> 5;
    const float4 f4z = make_float4(0.f, 0.f, 0.f, 0.f);

    const int lane = tid & 31, warp = tid >> 5;
    const int m0 = (warp & 3) * 16;
    const int cs = (warp >> 2) * 32;
    const int r8 = lane & 7, sel = lane >> 3;
    const int atrow = ((sel >> 1) & 1) * 8 + r8;
    const int atcol = m0 + (sel & 1) * 8;
    const int brow = lane & 15;
    const int gid = lane >> 2, tig = lane & 3;

    float u[4][4] = {};
    float v[4][4] = {};

    float4 qa[2], qb[2], xa[2], xb[2];
    auto ldchunk = [&](int ci) {
        #pragma unroll
        for (int q = 0; q < 2; q++) {
            int f = tid + 256 * q;
            int row = f >> 4, k4 = (f & 15) * 4;
            int n = ci * 32 + row;
            bool ok = (n < N);
            qa[q] = ok ? *(const float4*)(Qr + (long)n * 64 + k4) : f4z;
            qb[q] = ok ? *(const float4*)(Qi + (long)n * 64 + k4) : f4z;
            xa[q] = ok ? *(const float4*)(re + (long)n * 128 + c0 + k4) : f4z;
            xb[q] = ok ? *(const float4*)(im + (long)n * 128 + c0 + k4) : f4z;
        }
    };

    ldchunk(s);
    for (int t = 0;; t++) {
        int ci = s + t * NS1;
        if (ci >= nchunks) break;
        #pragma unroll
        for (int q = 0; q < 2; q++) {
            int f = tid + 256 * q;
            int row = f >> 4, k4 = (f & 15) * 4;
            cvst(&sQrh[row][k4], &sQrl[row][k4], qa[q]);
            cvst(&sQih[row][k4], &sQil[row][k4], qb[q]);
            cvst(&sXrh[row][k4], &sXrl[row][k4], xa[q]);
            cvst(&sXih[row][k4], &sXil[row][k4], xb[q]);
        }
        __syncthreads();
        int cin = ci + NS1;
        if (cin < nchunks) ldchunk(cin);

        #pragma unroll
        for (int ks = 0; ks < 2; ks++) {
            const int n0k = ks * 16;
            uint32_t qrh[4], qrl[4], qih[4], qil[4], nqh[4], nql[4];
            ldmAT(qrh, sadr(&sQrh[n0k + atrow][atcol]));
            ldmAT(qrl, sadr(&sQrl[n0k + atrow][atcol]));
            ldmAT(qih, sadr(&sQih[n0k + atrow][atcol]));
            ldmAT(qil, sadr(&sQil[n0k + atrow][atcol]));
            NEG4(nqh, qrh);
            NEG4(nql, qrl);
            #pragma unroll
            for (int nt = 0; nt < 4; nt++) {
                uint32_t xh[2], xl[2], yh[2], yl[2];
                ldmBT(xh, sadr(&sXrh[n0k + brow][cs + nt * 8]));
                ldmBT(xl, sadr(&sXrl[n0k + brow][cs + nt * 8]));
                ldmBT(yh, sadr(&sXih[n0k + brow][cs + nt * 8]));
                ldmBT(yl, sadr(&sXil[n0k + brow][cs + nt * 8]));
                mma(u[nt], qrh, xh); mma(u[nt], qrh, xl); mma(u[nt], qrl, xh);
                mma(u[nt], qih, yh); mma(u[nt], qih, yl); mma(u[nt], qil, yh);
                mma(v[nt], qih, xh); mma(v[nt], qih, xl); mma(v[nt], qil, xh);
                mma(v[nt], nqh, yh); mma(v[nt], nqh, yl); mma(v[nt], nql, yh);
            }
        }
        __syncthreads();
    }

    #pragma unroll
    for (int nt = 0; nt < 4; nt++) {
        int k = m0 + gid;
        int c = c0 + cs + nt * 8 + tig * 2;
        *(float2*)&g_part[0][s][k][c]     = make_float2(u[nt][0], u[nt][1]);
        *(float2*)&g_part[0][s][k + 8][c] = make_float2(u[nt][2], u[nt][3]);
        *(float2*)&g_part[1][s][k][c]     = make_float2(v[nt][0], v[nt][1]);
        *(float2*)&g_part[1][s][k + 8][c] = make_float2(v[nt][2], v[nt][3]);
    }
}

// ---------------------------------------------------------------------------
// Kernel 2a: reduce partials over splits, scale row k by TT = Ritz[k]^ld.
// ---------------------------------------------------------------------------
__global__ __launch_bounds__(256) void k2a_reduce(
    const float* __restrict__ Ritz, const int* __restrict__ ldp, int nsplit)
{
    __shared__ float red[256];
    const int o   = threadIdx.x & 31;
    const int seg = threadIdx.x >> 5;
    const int t   = blockIdx.x * 32 + o;
    const int uv  = t >> 13;
    const int rem = t & 8191;

    const float* p = &g_part[uv][0][0][0] + rem;
    float sum = 0.f;
    for (int s2 = seg; s2 < nsplit; s2 += 8) sum += p[(long)s2 * 8192];
    red[threadIdx.x] = sum;
    __syncthreads();

    if (threadIdx.x < 32) {
        #pragma unroll
        for (int g = 1; g < 8; g++) sum += red[g * 32 + o];
        int k = rem >> 7;
        int ld = *ldp;
        float rz = Ritz[k];
        float tt = 1.f;
        for (int i = 0; i < ld; i++) tt *= rz;
        (&g_UV[0][0][0])[t] = tt * sum;
    }
}

// ---------------------------------------------------------------------------
// Kernel 2b: P = U' @ W, R = V' @ W  ([64,128]@[128,128]); fp32 outputs.
// ---------------------------------------------------------------------------
__global__ __launch_bounds__(256) void k2b_pr(const float* __restrict__ W)
{
    __shared__ float sA[64 * 68];
    __shared__ float sW[64 * 64];

    const int m   = blockIdx.x;
    const int cp0 = blockIdx.y * 64;
    const int tx = threadIdx.x, ty = threadIdx.y;
    const int tid = ty * 16 + tx;

    float acc[4][4] = {};

    for (int cc = 0; cc < 128; cc += 64) {
        #pragma unroll
        for (int q = 0; q < 4; q++) {
            int f   = tid + 256 * q;
            int row = f >> 4;
            int c4  = (f & 15) * 4;
            *(float4*)&sA[row * 68 + c4] = *(const float4*)&g_UV[m][row][cc + c4];
            *(float4*)&sW[row * 64 + c4] = *(const float4*)(W + (cc + row) * 128 + cp0 + c4);
        }
        __syncthreads();

        #pragma unroll 4
        for (int r = 0; r < 64; r++) {
            float a[4];
            #pragma unroll
            for (int i = 0; i < 4; i++) a[i] = sA[(ty * 4 + i) * 68 + r];
            float4 w4 = *(float4*)&sW[r * 64 + tx * 4];
            float wj[4] = {w4.x, w4.y, w4.z, w4.w};
            #pragma unroll
            for (int i = 0; i < 4; i++)
                #pragma unroll
                for (int j = 0; j < 4; j++)
                    acc[i][j] += a[i] * wj[j];
        }
        __syncthreads();
    }

    #pragma unroll
    for (int i = 0; i < 4; i++)
        *(float4*)&g_PR[m][ty * 4 + i][cp0 + tx * 4] =
            make_float4(acc[i][0], acc[i][1], acc[i][2], acc[i][3]);
}

// ---------------------------------------------------------------------------
// Kernel 3: TF32 single-pass. sr = Qr@P + Qi@R ; si = Qi@P - Qr@R.
// grid (ceil(N/64), 2 c-halves), block 256, 2 CTA/SM:
// 8 warps = 4 n-slabs(16) x 2 c-sub(32). 4 k-phases of 16 (2 k8 steps each).
// Fragment-major smem staging -> plain conflict-free LDS.128/LDS.64, no
// ldmatrix, no bf16 converts. Register prefetch of next phase under MMA.
// ---------------------------------------------------------------------------
__global__ __launch_bounds__(256, 2) void k3_out(
    const float* __restrict__ Qr, const float* __restrict__ Qi,
    const float* __restrict__ re, const float* __restrict__ im,
    float* __restrict__ out, int N)
{
    // [m][ks][slab][lane][j]  (Q fragments, tf32 bits)
    __shared__ uint32_t sQ[2][2][4][32][4];     // 8 KB
    // [m][ks][csub][nt][lane][bj]  (P/R fragments)
    __shared__ uint32_t sB[2][2][2][4][32][2];  // 8 KB

    const int n0 = blockIdx.x * 64;
    const int c0 = blockIdx.y * 64;
    const int tid = threadIdx.x;
    const float4 f4z = make_float4(0.f, 0.f, 0.f, 0.f);

    const int lane = tid & 31, warp = tid >> 5;
    const int slab = warp & 3;            // n-slab of 16
    const int csub = warp >> 2;           // c-sub of 32
    const int gid = lane >> 2, tig = lane & 3;

    // staging coords (Q): thread covers Qr/Qi[n0+qn][kk+qk4 .. +3]
    const int qn  = tid >> 2;             // 0..63
    const int qk4 = (tid & 3) * 4;        // 0,4,8,12
    const int q_ks  = qk4 >> 3;           // 0..1
    const int q_khi = (qk4 >> 2) & 1;     // 0..1
    const int q_slab = qn >> 4;
    const int q_gid  = qn & 7;
    const int q_hi   = (qn >> 3) & 1;
    // staging coords (B): thread covers P/R[kk+bk][c0+bc4 .. +3]
    const int bk  = tid >> 4;             // 0..15
    const int bc4 = (tid & 15) * 4;       // 0..60
    const int b_ks  = bk >> 3;
    const int b_t4  = bk & 3;
    const int b_bj  = (bk >> 2) & 1;
    const int b_csub = bc4 >> 5;

    float4 qa, qb, pa, ra;
    auto ldphase = [&](int ph) {
        const int kk = ph * 16;
        int n = n0 + qn;
        bool ok = (n < N);
        qa = ok ? *(const float4*)(Qr + (long)n * 64 + kk + qk4) : f4z;
        qb = ok ? *(const float4*)(Qi + (long)n * 64 + kk + qk4) : f4z;
        pa = *(const float4*)&g_PR[0][kk + bk][c0 + bc4];
        ra = *(const float4*)&g_PR[1][kk + bk][c0 + bc4];
    };
    auto stphase = [&]() {
        const int j = q_hi + 2 * q_khi;
        sQ[0][q_ks][q_slab][q_gid * 4 + 0][j] = tf32c(qa.x);
        sQ[0][q_ks][q_slab][q_gid * 4 + 1][j] = tf32c(qa.y);
        sQ[0][q_ks][q_slab][q_gid * 4 + 2][j] = tf32c(qa.z);
        sQ[0][q_ks][q_slab][q_gid * 4 + 3][j] = tf32c(qa.w);
        sQ[1][q_ks][q_slab][q_gid * 4 + 0][j] = tf32c(qb.x);
        sQ[1][q_ks][q_slab][q_gid * 4 + 1][j] = tf32c(qb.y);
        sQ[1][q_ks][q_slab][q_gid * 4 + 2][j] = tf32c(qb.z);
        sQ[1][q_ks][q_slab][q_gid * 4 + 3][j] = tf32c(qb.w);
        float pv[4] = {pa.x, pa.y, pa.z, pa.w};
        float rv[4] = {ra.x, ra.y, ra.z, ra.w};
        #pragma unroll
        for (int e = 0; e < 4; e++) {
            int cl = (bc4 & 31) + e;
            int nt = cl >> 3, bgid = cl & 7;
            sB[0][b_ks][b_csub][nt][bgid * 4 + b_t4][b_bj] = tf32c(pv[e]);
            sB[1][b_ks][b_csub][nt][bgid * 4 + b_t4][b_bj] = tf32c(rv[e]);
        }
    };

    float sr[4][4] = {};
    float si[4][4] = {};

    ldphase(0);
    #pragma unroll
    for (int ph = 0; ph < 4; ph++) {
        if (ph) __syncthreads();          // prior phase fully consumed
        stphase();
        __syncthreads();
        if (ph < 3) ldphase(ph + 1);      // global prefetch under MMA

        #pragma unroll
        for (int ks = 0; ks < 2; ks++) {
            uint32_t qr[4], qi[4], nqr[4];
            *(uint4*)qr = *(const uint4*)&sQ[0][ks][slab][lane][0];
            *(uint4*)qi = *(const uint4*)&sQ[1][ks][slab][lane][0];
            #pragma unroll
            for (int e = 0; e < 4; e++) nqr[e] = qr[e] ^ 0x80000000u;
            #pragma unroll
            for (int nt = 0; nt < 4; nt++) {
                uint32_t p[2], r[2];
                *(uint2*)p = *(const uint2*)&sB[0][ks][csub][nt][lane][0];
                *(uint2*)r = *(const uint2*)&sB[1][ks][csub][nt][lane][0];
                mma_tf32(sr[nt], qr, p);
                mma_tf32(sr[nt], qi, r);
                mma_tf32(si[nt], qi, p);
                mma_tf32(si[nt], nqr, r);
            }
        }
    }

    // epilogue: masked-ReLU add, write out
    const long NC = (long)N * 128;
    #pragma unroll
    for (int nt = 0; nt < 4; nt++) {
        int c = c0 + csub * 32 + nt * 8 + tig * 2;
        #pragma unroll
        for (int h = 0; h < 2; h++) {
            int n = n0 + slab * 16 + gid + 8 * h;
            if (n >= N) continue;
            long base = (long)n * 128 + c;
            float2 rvv = *(const float2*)(re + base);
            float2 ivv = *(const float2*)(im + base);
            float sr0 = sr[nt][2 * h + 0], sr1 = sr[nt][2 * h + 1];
            float si0 = si[nt][2 * h + 0], si1 = si[nt][2 * h + 1];
            float mk0 = (sr0 >= 0.f) ? 1.f : 0.f;
            float mk1 = (sr1 >= 0.f) ? 1.f : 0.f;
            *(float2*)(out + base)      = make_float2(rvv.x + mk0 * sr0, rvv.y + mk1 * sr1);
            *(float2*)(out + NC + base) = make_float2(ivv.x + mk0 * si0, ivv.y + mk1 * si1);
        }
    }
}

// ---------------------------------------------------------------------------
extern "C" void kernel_launch(void* const* d_in, const int* in_sizes, int n_in,
                              void* d_out, int out_size)
{
    const float* real  = (const float*)d_in[0];
    const float* imag  = (const float*)d_in[1];
    const float* Qreal = (const float*)d_in[2];
    const float* Qimag = (const float*)d_in[3];
    const float* Ritz  = (const float*)d_in[4];
    const float* W     = (const float*)d_in[5];
    const int*   ldp   = (const int*)d_in[6];
    float* out = (float*)d_out;

    int N = in_sizes[0] / CDIM;
    int nchunks = (N + 31) / 32;
    int nsplit = (nchunks < NS1) ? nchunks : NS1;

    k1_partial<<<dim3(NS1, 2), 256>>>(Qreal, Qimag, real, imag, N);
    k2a_reduce<<<512, 256>>>(Ritz, ldp, nsplit);
    k2b_pr<<<dim3(2, 2), dim3(16, 16)>>>(W);
    k3_out<<<dim3((N + 63) / 64, 2), 256>>>(Qreal, Qimag, real, imag, out, N);
}

// round 15
// speedup vs baseline: 1.6057x; 1.6057x over previous
#include <cuda_runtime.h>
#include <cuda_fp16.h>
#include <cstdint>

#define CDIM 128
#define NS1 74
#define PQ 72   // fp16 tile pitch (144B): conflict-free LDSM
#define PQA 40  // fp16 tile pitch (80B): conflict-free LDSM

__device__ float g_part[2][80][64][CDIM];   // 5.2 MB
__device__ float g_UV[2][64][CDIM];
__device__ unsigned short g_Ph[64][128];    // fp16 P
__device__ unsigned short g_Rh[64][128];    // fp16 R

// ---------------------------------------------------------------------------
// helpers
// ---------------------------------------------------------------------------
__device__ __forceinline__ unsigned sadr(const void* p) {
    return (unsigned)__cvta_generic_to_shared(p);
}
// pack two fp32 -> fp16x2 (x0 in low half)
__device__ __forceinline__ uint32_t pkh2(float x0, float x1) {
    uint32_t d;
    asm("cvt.rn.f16x2.f32 %0, %2, %1;" : "=r"(d) : "f"(x0), "f"(x1));
    return d;
}
// convert float4 -> fp16, store 8B
__device__ __forceinline__ void cvsth(unsigned short* hp, float4 a) {
    ((uint32_t*)hp)[0] = pkh2(a.x, a.y);
    ((uint32_t*)hp)[1] = pkh2(a.z, a.w);
}
__device__ __forceinline__ void ldmA(uint32_t* a, unsigned addr) {
    asm volatile("ldmatrix.sync.aligned.m8n8.x4.shared.b16 {%0,%1,%2,%3},[%4];"
        : "=r"(a[0]), "=r"(a[1]), "=r"(a[2]), "=r"(a[3]) : "r"(addr));
}
__device__ __forceinline__ void ldmAT(uint32_t* a, unsigned addr) {
    asm volatile("ldmatrix.sync.aligned.m8n8.x4.trans.shared.b16 {%0,%1,%2,%3},[%4];"
        : "=r"(a[0]), "=r"(a[1]), "=r"(a[2]), "=r"(a[3]) : "r"(addr));
}
__device__ __forceinline__ void ldmBT(uint32_t* b, unsigned addr) {
    asm volatile("ldmatrix.sync.aligned.m8n8.x2.trans.shared.b16 {%0,%1},[%2];"
        : "=r"(b[0]), "=r"(b[1]) : "r"(addr));
}
__device__ __forceinline__ void mma_h(float* d, const uint32_t* a, const uint32_t* b) {
    asm volatile("mma.sync.aligned.m16n8k16.row.col.f32.f16.f16.f32 "
        "{%0,%1,%2,%3},{%4,%5,%6,%7},{%8,%9},{%0,%1,%2,%3};"
        : "+f"(d[0]), "+f"(d[1]), "+f"(d[2]), "+f"(d[3])
        : "r"(a[0]), "r"(a[1]), "r"(a[2]), "r"(a[3]), "r"(b[0]), "r"(b[1]));
}
#define NEG4H(dst, src) { dst[0]=src[0]^0x80008000u; dst[1]=src[1]^0x80008000u; \
                          dst[2]=src[2]^0x80008000u; dst[3]=src[3]^0x80008000u; }

// ---------------------------------------------------------------------------
// Kernel 1: U/V partials, fp16 single-pass. Chunk loop + register prefetch.
//   U[k,c] = sum_n Qr[n,k]*re[n,c] + Qi[n,k]*im[n,c]
//   V[k,c] = sum_n Qi[n,k]*re[n,c] - Qr[n,k]*im[n,c]
// grid (74, 2 c-halves), block 256: 8 warps = 4 k-slabs(16) x 2 c-sub(32).
// ---------------------------------------------------------------------------
__global__ __launch_bounds__(256, 1) void k1_partial(
    const float* __restrict__ Qr, const float* __restrict__ Qi,
    const float* __restrict__ re, const float* __restrict__ im, int N)
{
    __shared__ unsigned short sQr[32][PQ], sQi[32][PQ];
    __shared__ unsigned short sRe[32][PQ], sIm[32][PQ];

    const int s  = blockIdx.x;
    const int c0 = blockIdx.y * 64;
    const int tid = threadIdx.x;
    const int nchunks = (N + 31) >> 5;
    const float4 f4z = make_float4(0.f, 0.f, 0.f, 0.f);

    const int lane = tid & 31, warp = tid >> 5;
    const int m0 = (warp & 3) * 16;        // k-slab
    const int cs = (warp >> 2) * 32;       // c-sub
    const int r8 = lane & 7, sel = lane >> 3;
    const int atrow = ((sel >> 1) & 1) * 8 + r8;
    const int atcol = m0 + (sel & 1) * 8;
    const int brow = lane & 15;
    const int gid = lane >> 2, tig = lane & 3;

    float u[4][4] = {};
    float v[4][4] = {};

    float4 qa[2], qb[2], xa[2], xb[2];
    auto ldchunk = [&](int ci) {
        #pragma unroll
        for (int q = 0; q < 2; q++) {
            int f = tid + 256 * q;
            int row = f >> 4, k4 = (f & 15) * 4;
            int n = ci * 32 + row;
            bool ok = (n < N);
            qa[q] = ok ? *(const float4*)(Qr + (long)n * 64 + k4) : f4z;
            qb[q] = ok ? *(const float4*)(Qi + (long)n * 64 + k4) : f4z;
            xa[q] = ok ? *(const float4*)(re + (long)n * 128 + c0 + k4) : f4z;
            xb[q] = ok ? *(const float4*)(im + (long)n * 128 + c0 + k4) : f4z;
        }
    };

    ldchunk(s);
    for (int t = 0;; t++) {
        int ci = s + t * NS1;
        if (ci >= nchunks) break;                     // CTA-uniform
        #pragma unroll
        for (int q = 0; q < 2; q++) {
            int f = tid + 256 * q;
            int row = f >> 4, k4 = (f & 15) * 4;
            cvsth(&sQr[row][k4], qa[q]);
            cvsth(&sQi[row][k4], qb[q]);
            cvsth(&sRe[row][k4], xa[q]);
            cvsth(&sIm[row][k4], xb[q]);
        }
        __syncthreads();
        int cin = ci + NS1;
        if (cin < nchunks) ldchunk(cin);              // prefetch under MMA

        #pragma unroll
        for (int ks = 0; ks < 2; ks++) {
            const int n0k = ks * 16;
            uint32_t qr[4], qi[4], nq[4];
            ldmAT(qr, sadr(&sQr[n0k + atrow][atcol]));
            ldmAT(qi, sadr(&sQi[n0k + atrow][atcol]));
            NEG4H(nq, qr);
            #pragma unroll
            for (int nt = 0; nt < 4; nt++) {
                uint32_t x[2], y[2];
                ldmBT(x, sadr(&sRe[n0k + brow][cs + nt * 8]));
                ldmBT(y, sadr(&sIm[n0k + brow][cs + nt * 8]));
                mma_h(u[nt], qr, x);
                mma_h(u[nt], qi, y);
                mma_h(v[nt], qi, x);
                mma_h(v[nt], nq, y);
            }
        }
        __syncthreads();
    }

    #pragma unroll
    for (int nt = 0; nt < 4; nt++) {
        int k = m0 + gid;
        int c = c0 + cs + nt * 8 + tig * 2;
        *(float2*)&g_part[0][s][k][c]     = make_float2(u[nt][0], u[nt][1]);
        *(float2*)&g_part[0][s][k + 8][c] = make_float2(u[nt][2], u[nt][3]);
        *(float2*)&g_part[1][s][k][c]     = make_float2(v[nt][0], v[nt][1]);
        *(float2*)&g_part[1][s][k + 8][c] = make_float2(v[nt][2], v[nt][3]);
    }
}

// ---------------------------------------------------------------------------
// Kernel 2a: reduce partials over splits, scale row k by TT = Ritz[k]^ld.
// ---------------------------------------------------------------------------
__global__ __launch_bounds__(256) void k2a_reduce(
    const float* __restrict__ Ritz, const int* __restrict__ ldp, int nsplit)
{
    __shared__ float red[256];
    const int o   = threadIdx.x & 31;
    const int seg = threadIdx.x >> 5;
    const int t   = blockIdx.x * 32 + o;
    const int uv  = t >> 13;
    const int rem = t & 8191;

    const float* p = &g_part[uv][0][0][0] + rem;
    float sum = 0.f;
    for (int s2 = seg; s2 < nsplit; s2 += 8) sum += p[(long)s2 * 8192];
    red[threadIdx.x] = sum;
    __syncthreads();

    if (threadIdx.x < 32) {
        #pragma unroll
        for (int g = 1; g < 8; g++) sum += red[g * 32 + o];
        int k = rem >> 7;
        int ld = *ldp;
        float rz = Ritz[k];
        float tt = 1.f;
        for (int i = 0; i < ld; i++) tt *= rz;
        (&g_UV[0][0][0])[t] = tt * sum;
    }
}

// ---------------------------------------------------------------------------
// Kernel 2b: P = U' @ W, R = V' @ W  ([64,128]@[128,128]); fp16 outputs.
// ---------------------------------------------------------------------------
__global__ __launch_bounds__(256) void k2b_pr(const float* __restrict__ W)
{
    __shared__ float sA[64 * 68];
    __shared__ float sW[64 * 64];

    const int m   = blockIdx.x;
    const int cp0 = blockIdx.y * 64;
    const int tx = threadIdx.x, ty = threadIdx.y;
    const int tid = ty * 16 + tx;

    float acc[4][4] = {};

    for (int cc = 0; cc < 128; cc += 64) {
        #pragma unroll
        for (int q = 0; q < 4; q++) {
            int f   = tid + 256 * q;
            int row = f >> 4;
            int c4  = (f & 15) * 4;
            *(float4*)&sA[row * 68 + c4] = *(const float4*)&g_UV[m][row][cc + c4];
            *(float4*)&sW[row * 64 + c4] = *(const float4*)(W + (cc + row) * 128 + cp0 + c4);
        }
        __syncthreads();

        #pragma unroll 4
        for (int r = 0; r < 64; r++) {
            float a[4];
            #pragma unroll
            for (int i = 0; i < 4; i++) a[i] = sA[(ty * 4 + i) * 68 + r];
            float4 w4 = *(float4*)&sW[r * 64 + tx * 4];
            float wj[4] = {w4.x, w4.y, w4.z, w4.w};
            #pragma unroll
            for (int i = 0; i < 4; i++)
                #pragma unroll
                for (int j = 0; j < 4; j++)
                    acc[i][j] += a[i] * wj[j];
        }
        __syncthreads();
    }

    unsigned short (*Dh)[128] = (m == 0) ? g_Ph : g_Rh;
    #pragma unroll
    for (int i = 0; i < 4; i++) {
        int k = ty * 4 + i;
        int c = cp0 + tx * 4;
        ((uint32_t*)&Dh[k][c])[0] = pkh2(acc[i][0], acc[i][1]);
        ((uint32_t*)&Dh[k][c])[1] = pkh2(acc[i][2], acc[i][3]);
    }
}

// ---------------------------------------------------------------------------
// Kernel 3: fp16 single-pass. sr = Qr@P + Qi@R ; si = Qi@P - Qr@R.
// grid (ceil(N/64), 2 c-halves), block 128, 2 CTA/SM (R9 structure):
// 4 warps = 4 n-slabs(16); each warp covers the full 64-c half (8 n8-tiles).
// Two k-phases of 32; batched reg-first loads per phase.
// ---------------------------------------------------------------------------
__global__ __launch_bounds__(128, 2) void k3_out(
    const float* __restrict__ Qr, const float* __restrict__ Qi,
    const float* __restrict__ re, const float* __restrict__ im,
    float* __restrict__ out, int N)
{
    __shared__ unsigned short sQr[64][PQA], sQi[64][PQA];
    __shared__ unsigned short sP[32][PQ], sR[32][PQ];

    const int n0 = blockIdx.x * 64;
    const int c0 = blockIdx.y * 64;
    const int tid = threadIdx.x;
    const float4 f4z = make_float4(0.f, 0.f, 0.f, 0.f);

    const int lane = tid & 31, warp = tid >> 5;
    const int m0 = warp * 16;                 // n-slab
    const int arow = m0 + (lane & 15);
    const int acol8 = (lane >> 4) * 8;
    const int brow = lane & 15;
    const int gid = lane >> 2, tig = lane & 3;

    float sr[8][4] = {};
    float si[8][4] = {};

    #pragma unroll
    for (int ph = 0; ph < 2; ph++) {
        const int kk = ph * 32;
        // batched reg-first loads: Q k-half (fp32) + P/R k-half (fp16)
        float4 qa[4], qb[4];
        uint4 pv[2], rv[2];
        #pragma unroll
        for (int q = 0; q < 4; q++) {
            int f = tid + 128 * q;
            int row = f >> 3, k4 = (f & 7) * 4;
            int n = n0 + row;
            bool ok = (n < N);
            qa[q] = ok ? *(const float4*)(Qr + (long)n * 64 + kk + k4) : f4z;
            qb[q] = ok ? *(const float4*)(Qi + (long)n * 64 + kk + k4) : f4z;
        }
        #pragma unroll
        for (int q = 0; q < 2; q++) {
            int f = tid + 128 * q;
            int row = f >> 3, cu = f & 7;
            pv[q] = *(const uint4*)&g_Ph[kk + row][c0 + cu * 8];
            rv[q] = *(const uint4*)&g_Rh[kk + row][c0 + cu * 8];
        }
        if (ph) __syncthreads();   // protect previous phase reads
        #pragma unroll
        for (int q = 0; q < 4; q++) {
            int f = tid + 128 * q;
            int row = f >> 3, k4 = (f & 7) * 4;
            cvsth(&sQr[row][k4], qa[q]);
            cvsth(&sQi[row][k4], qb[q]);
        }
        #pragma unroll
        for (int q = 0; q < 2; q++) {
            int f = tid + 128 * q;
            int row = f >> 3, cu = f & 7;
            *(uint4*)&sP[row][cu * 8] = pv[q];
            *(uint4*)&sR[row][cu * 8] = rv[q];
        }
        __syncthreads();

        #pragma unroll
        for (int ks = 0; ks < 2; ks++) {
            const int k0 = ks * 16;
            uint32_t qr[4], qi[4], nq[4];
            ldmA(qr, sadr(&sQr[arow][k0 + acol8]));
            ldmA(qi, sadr(&sQi[arow][k0 + acol8]));
            NEG4H(nq, qr);
            #pragma unroll
            for (int nt = 0; nt < 8; nt++) {
                uint32_t p[2], r[2];
                ldmBT(p, sadr(&sP[k0 + brow][nt * 8]));
                ldmBT(r, sadr(&sR[k0 + brow][nt * 8]));
                mma_h(sr[nt], qr, p);
                mma_h(sr[nt], qi, r);
                mma_h(si[nt], qi, p);
                mma_h(si[nt], nq, r);
            }
        }
    }

    // epilogue: masked-ReLU add, write out
    const long NC = (long)N * 128;
    #pragma unroll
    for (int nt = 0; nt < 8; nt++) {
        int c = c0 + nt * 8 + tig * 2;
        #pragma unroll
        for (int h = 0; h < 2; h++) {
            int n = n0 + m0 + gid + 8 * h;
            if (n >= N) continue;
            long base = (long)n * 128 + c;
            float2 rvv = *(const float2*)(re + base);
            float2 ivv = *(const float2*)(im + base);
            float sr0 = sr[nt][2 * h + 0], sr1 = sr[nt][2 * h + 1];
            float si0 = si[nt][2 * h + 0], si1 = si[nt][2 * h + 1];
            float mk0 = (sr0 >= 0.f) ? 1.f : 0.f;
            float mk1 = (sr1 >= 0.f) ? 1.f : 0.f;
            *(float2*)(out + base)      = make_float2(rvv.x + mk0 * sr0, rvv.y + mk1 * sr1);
            *(float2*)(out + NC + base) = make_float2(ivv.x + mk0 * si0, ivv.y + mk1 * si1);
        }
    }
}

// ---------------------------------------------------------------------------
extern "C" void kernel_launch(void* const* d_in, const int* in_sizes, int n_in,
                              void* d_out, int out_size)
{
    const float* real  = (const float*)d_in[0];
    const float* imag  = (const float*)d_in[1];
    const float* Qreal = (const float*)d_in[2];
    const float* Qimag = (const float*)d_in[3];
    const float* Ritz  = (const float*)d_in[4];
    const float* W     = (const float*)d_in[5];
    const int*   ldp   = (const int*)d_in[6];
    float* out = (float*)d_out;

    int N = in_sizes[0] / CDIM;
    int nchunks = (N + 31) / 32;
    int nsplit = (nchunks < NS1) ? nchunks : NS1;

    k1_partial<<<dim3(NS1, 2), 256>>>(Qreal, Qimag, real, imag, N);
    k2a_reduce<<<512, 256>>>(Ritz, ldp, nsplit);
    k2b_pr<<<dim3(2, 2), dim3(16, 16)>>>(W);
    k3_out<<<dim3((N + 63) / 64, 2), 128>>>(Qreal, Qimag, real, imag, out, N);
}